// round 1
// baseline (speedup 1.0000x reference)
#include <cuda_runtime.h>

// Problem shapes (fixed by the dataset)
static const int D_FEAT = 4096;   // d
static const int N_SAMP = 8192;   // n
static const int OUT_D  = 2048;   // out_dim

// Scratch (no allocations allowed -> __device__ globals)
__device__ float g_mu[OUT_D];
__device__ float g_tmp[(size_t)OUT_D * D_FEAT];   // 32 MB intermediate [out_dim, d]

// ---------------------------------------------------------------------------
// Row mean of Psi: mu[o] = (1/n) * sum_n Psi[o, n]
// ---------------------------------------------------------------------------
__global__ void rowmean_kernel(const float* __restrict__ Psi, float* __restrict__ mu) {
    const int row = blockIdx.x;
    const float4* p = reinterpret_cast<const float4*>(Psi) + (size_t)row * (N_SAMP / 4);
    float s = 0.f;
    for (int i = threadIdx.x; i < N_SAMP / 4; i += 256) {
        float4 v = p[i];
        s += (v.x + v.y) + (v.z + v.w);
    }
    __shared__ float red[256];
    red[threadIdx.x] = s;
    __syncthreads();
    #pragma unroll
    for (int off = 128; off > 0; off >>= 1) {
        if (threadIdx.x < off) red[threadIdx.x] += red[threadIdx.x + off];
        __syncthreads();
    }
    if (threadIdx.x == 0) mu[row] = red[0] * (1.0f / N_SAMP);
}

// ---------------------------------------------------------------------------
// SGEMM 128x128x8, 256 threads, 8x8 per thread, double-buffered SMEM.
//   TRANS_B = true : C[M,N] = A[M,K] * B[N,K]^T   (NT; both K-contiguous)
//   TRANS_B = false: C[M,N] = A[M,K] * B[K,N]     (NN)
//   SUB_MEAN: subtract mu[row] from A elements on load (fused centering)
// Assumes M,N % 128 == 0 and K % 8 == 0 (true for these shapes).
// ---------------------------------------------------------------------------
template <bool TRANS_B, bool SUB_MEAN>
__global__ void __launch_bounds__(256, 2)
sgemm128(const float* __restrict__ A, const float* __restrict__ B,
         const float* __restrict__ mu,
         float* __restrict__ C, int M, int N, int K)
{
    __shared__ float As[2][8][128];
    __shared__ float Bs[2][8][128];

    const int tid = threadIdx.x;
    const int tx  = tid & 15;        // 0..15 -> 8 cols each
    const int ty  = tid >> 4;        // 0..15 -> 8 rows each
    const int m0  = blockIdx.y * 128;
    const int n0  = blockIdx.x * 128;

    // A loader: 128 rows x 8 cols, one float4 along K per thread
    const int arow = tid >> 1;            // 0..127
    const int acol = (tid & 1) * 4;       // 0 or 4
    const float sub = SUB_MEAN ? mu[m0 + arow] : 0.0f;
    const float* Aptr = A + (size_t)(m0 + arow) * K + acol;

    // B loader
    int brow, bcol;
    if (TRANS_B) { brow = tid >> 1; bcol = (tid & 1) * 4; }    // [N,K] tile, transpose-store
    else         { brow = tid >> 5; bcol = (tid & 31) * 4; }   // [K,N] tile, direct float4
    const float* Bptr = TRANS_B ? (B + (size_t)(n0 + brow) * K + bcol)
                                : (B + (size_t)brow * N + (n0 + bcol));

    float acc[8][8];
    #pragma unroll
    for (int i = 0; i < 8; ++i)
        #pragma unroll
        for (int j = 0; j < 8; ++j) acc[i][j] = 0.0f;

    // Preload first K-tile
    {
        float4 av = *reinterpret_cast<const float4*>(Aptr);
        As[0][acol + 0][arow] = av.x - sub;
        As[0][acol + 1][arow] = av.y - sub;
        As[0][acol + 2][arow] = av.z - sub;
        As[0][acol + 3][arow] = av.w - sub;
        float4 bv = *reinterpret_cast<const float4*>(Bptr);
        if (TRANS_B) {
            Bs[0][bcol + 0][brow] = bv.x;
            Bs[0][bcol + 1][brow] = bv.y;
            Bs[0][bcol + 2][brow] = bv.z;
            Bs[0][bcol + 3][brow] = bv.w;
        } else {
            *reinterpret_cast<float4*>(&Bs[0][brow][bcol]) = bv;
        }
    }
    __syncthreads();

    int buf = 0;
    for (int kt = 0; kt < K; kt += 8) {
        const bool more = (kt + 8) < K;
        float4 an, bn;
        if (more) {
            an = *reinterpret_cast<const float4*>(Aptr + kt + 8);
            bn = TRANS_B
               ? *reinterpret_cast<const float4*>(Bptr + kt + 8)
               : *reinterpret_cast<const float4*>(Bptr + (size_t)(kt + 8) * N);
        }

        #pragma unroll
        for (int k = 0; k < 8; ++k) {
            float4 a0 = *reinterpret_cast<const float4*>(&As[buf][k][ty * 8]);
            float4 a1 = *reinterpret_cast<const float4*>(&As[buf][k][ty * 8 + 4]);
            float4 b0 = *reinterpret_cast<const float4*>(&Bs[buf][k][tx * 8]);
            float4 b1 = *reinterpret_cast<const float4*>(&Bs[buf][k][tx * 8 + 4]);
            float a[8] = {a0.x, a0.y, a0.z, a0.w, a1.x, a1.y, a1.z, a1.w};
            float b[8] = {b0.x, b0.y, b0.z, b0.w, b1.x, b1.y, b1.z, b1.w};
            #pragma unroll
            for (int i = 0; i < 8; ++i)
                #pragma unroll
                for (int j = 0; j < 8; ++j)
                    acc[i][j] += a[i] * b[j];
        }

        if (more) {
            const int nb = buf ^ 1;
            As[nb][acol + 0][arow] = an.x - sub;
            As[nb][acol + 1][arow] = an.y - sub;
            As[nb][acol + 2][arow] = an.z - sub;
            As[nb][acol + 3][arow] = an.w - sub;
            if (TRANS_B) {
                Bs[nb][bcol + 0][brow] = bn.x;
                Bs[nb][bcol + 1][brow] = bn.y;
                Bs[nb][bcol + 2][brow] = bn.z;
                Bs[nb][bcol + 3][brow] = bn.w;
            } else {
                *reinterpret_cast<float4*>(&Bs[nb][brow][bcol]) = bn;
            }
        }
        __syncthreads();
        buf ^= 1;
    }

    // Epilogue: float4 stores
    #pragma unroll
    for (int i = 0; i < 8; ++i) {
        float* c = C + (size_t)(m0 + ty * 8 + i) * N + n0 + tx * 8;
        *reinterpret_cast<float4*>(c)     = make_float4(acc[i][0], acc[i][1], acc[i][2], acc[i][3]);
        *reinterpret_cast<float4*>(c + 4) = make_float4(acc[i][4], acc[i][5], acc[i][6], acc[i][7]);
    }
}

// ---------------------------------------------------------------------------
// Launch: rowmean -> GEMM1 (Psi_c @ x^T -> tmp) -> GEMM2 (tmp @ x -> out)
// ---------------------------------------------------------------------------
extern "C" void kernel_launch(void* const* d_in, const int* in_sizes, int n_in,
                              void* d_out, int out_size) {
    (void)n_in; (void)out_size;

    const float* x;
    const float* Psi;
    if (in_sizes[0] == D_FEAT * N_SAMP) {       // x is [4096, 8192]
        x   = (const float*)d_in[0];
        Psi = (const float*)d_in[1];
    } else {
        x   = (const float*)d_in[1];
        Psi = (const float*)d_in[0];
    }
    float* out = (float*)d_out;

    float* mu  = nullptr;
    float* tmp = nullptr;
    cudaGetSymbolAddress((void**)&mu,  g_mu);
    cudaGetSymbolAddress((void**)&tmp, g_tmp);

    // 1) row means of Psi
    rowmean_kernel<<<OUT_D, 256>>>(Psi, mu);

    // 2) tmp[o,d] = sum_n (Psi[o,n]-mu[o]) * x[d,n]   (NT, fused centering)
    {
        dim3 grid(D_FEAT / 128, OUT_D / 128);   // (32, 16)
        sgemm128<true, true><<<grid, 256>>>(Psi, x, mu, tmp, OUT_D, D_FEAT, N_SAMP);
    }

    // 3) out[o,n] = sum_d tmp[o,d] * x[d,n]           (NN)
    {
        dim3 grid(N_SAMP / 128, OUT_D / 128);   // (64, 16)
        sgemm128<false, false><<<grid, 256>>>(tmp, x, nullptr, out, OUT_D, N_SAMP, D_FEAT);
    }
}

// round 3
// speedup vs baseline: 2.4666x; 2.4666x over previous
#include <cuda_runtime.h>
#include <cuda_bf16.h>
#include <cstdint>

// ---------------------------------------------------------------- shapes
#define D_FEAT 4096
#define N_SAMP 8192
#define OUT_D  2048

// ---------------------------------------------------------------- scratch
__device__ float g_mu[OUT_D];
__device__ __nv_bfloat16 g_psi_hi[(size_t)OUT_D * N_SAMP];
__device__ __nv_bfloat16 g_psi_lo[(size_t)OUT_D * N_SAMP];
__device__ __nv_bfloat16 g_x_hi[(size_t)D_FEAT * N_SAMP];
__device__ __nv_bfloat16 g_x_lo[(size_t)D_FEAT * N_SAMP];
__device__ __nv_bfloat16 g_xt_hi[(size_t)N_SAMP * D_FEAT];
__device__ __nv_bfloat16 g_xt_lo[(size_t)N_SAMP * D_FEAT];
__device__ __nv_bfloat16 g_tmp_hi[(size_t)OUT_D * D_FEAT];
__device__ __nv_bfloat16 g_tmp_lo[(size_t)OUT_D * D_FEAT];

// ---------------------------------------------------------------- helpers
__device__ __forceinline__ uint32_t smem_u32(const void* p) {
    uint32_t a;
    asm("{ .reg .u64 t; cvta.to.shared.u64 t, %1; cvt.u32.u64 %0, t; }" : "=r"(a) : "l"(p));
    return a;
}
__device__ __forceinline__ void cpasync16(uint32_t s, const void* g) {
    asm volatile("cp.async.cg.shared.global [%0], [%1], 16;" :: "r"(s), "l"(g));
}
__device__ __forceinline__ void cp_commit() {
    asm volatile("cp.async.commit_group;" ::: "memory");
}
__device__ __forceinline__ void cp_wait1() {
    asm volatile("cp.async.wait_group 1;" ::: "memory");
}
__device__ __forceinline__ void ldsm4(uint32_t* r, uint32_t addr) {
    asm volatile("ldmatrix.sync.aligned.m8n8.x4.shared.b16 {%0,%1,%2,%3}, [%4];"
                 : "=r"(r[0]), "=r"(r[1]), "=r"(r[2]), "=r"(r[3]) : "r"(addr));
}
__device__ __forceinline__ void mma16816(float* c, const uint32_t* a, const uint32_t* b) {
    asm volatile("mma.sync.aligned.m16n8k16.row.col.f32.bf16.bf16.f32 "
                 "{%0,%1,%2,%3}, {%4,%5,%6,%7}, {%8,%9}, {%0,%1,%2,%3};"
                 : "+f"(c[0]), "+f"(c[1]), "+f"(c[2]), "+f"(c[3])
                 : "r"(a[0]), "r"(a[1]), "r"(a[2]), "r"(a[3]), "r"(b[0]), "r"(b[1]));
}
__device__ __forceinline__ void split_f32(float v, __nv_bfloat16& h, __nv_bfloat16& l) {
    h = __float2bfloat16(v);
    l = __float2bfloat16(v - __bfloat162float(h));
}

// ---------------------------------------------------------------- rowmean
__global__ void rowmean_kernel(const float* __restrict__ Psi, float* __restrict__ mu) {
    const int row = blockIdx.x;
    const float4* p = reinterpret_cast<const float4*>(Psi) + (size_t)row * (N_SAMP / 4);
    float s = 0.f;
    for (int i = threadIdx.x; i < N_SAMP / 4; i += 256) {
        float4 v = p[i];
        s += (v.x + v.y) + (v.z + v.w);
    }
    __shared__ float red[256];
    red[threadIdx.x] = s;
    __syncthreads();
    #pragma unroll
    for (int off = 128; off > 0; off >>= 1) {
        if (threadIdx.x < off) red[threadIdx.x] += red[threadIdx.x + off];
        __syncthreads();
    }
    if (threadIdx.x == 0) mu[row] = red[0] * (1.0f / N_SAMP);
}

// ------------------------------------------------- Psi center + bf16 split
__global__ void center_split_kernel(const float* __restrict__ Psi, const float* __restrict__ mu,
                                    __nv_bfloat16* __restrict__ hi, __nv_bfloat16* __restrict__ lo) {
    size_t i = (size_t)blockIdx.x * 256 + threadIdx.x;
    float4 v = reinterpret_cast<const float4*>(Psi)[i];
    float m = mu[i >> 11];
    v.x -= m; v.y -= m; v.z -= m; v.w -= m;
    __nv_bfloat16 h0, l0, h1, l1, h2, l2, h3, l3;
    split_f32(v.x, h0, l0); split_f32(v.y, h1, l1);
    split_f32(v.z, h2, l2); split_f32(v.w, h3, l3);
    reinterpret_cast<ushort4*>(hi)[i] = make_ushort4(
        __bfloat16_as_ushort(h0), __bfloat16_as_ushort(h1),
        __bfloat16_as_ushort(h2), __bfloat16_as_ushort(h3));
    reinterpret_cast<ushort4*>(lo)[i] = make_ushort4(
        __bfloat16_as_ushort(l0), __bfloat16_as_ushort(l1),
        __bfloat16_as_ushort(l2), __bfloat16_as_ushort(l3));
}

// ------------------------------------------------- x bf16 split
__global__ void split_kernel(const float* __restrict__ in,
                             __nv_bfloat16* __restrict__ hi, __nv_bfloat16* __restrict__ lo) {
    size_t i = (size_t)blockIdx.x * 256 + threadIdx.x;
    float4 v = reinterpret_cast<const float4*>(in)[i];
    __nv_bfloat16 h0, l0, h1, l1, h2, l2, h3, l3;
    split_f32(v.x, h0, l0); split_f32(v.y, h1, l1);
    split_f32(v.z, h2, l2); split_f32(v.w, h3, l3);
    reinterpret_cast<ushort4*>(hi)[i] = make_ushort4(
        __bfloat16_as_ushort(h0), __bfloat16_as_ushort(h1),
        __bfloat16_as_ushort(h2), __bfloat16_as_ushort(h3));
    reinterpret_cast<ushort4*>(lo)[i] = make_ushort4(
        __bfloat16_as_ushort(l0), __bfloat16_as_ushort(l1),
        __bfloat16_as_ushort(l2), __bfloat16_as_ushort(l3));
}

// ------------------------------------------------- x transpose + bf16 split
__global__ void transpose_split_kernel(const float* __restrict__ x,
                                       __nv_bfloat16* __restrict__ xth,
                                       __nv_bfloat16* __restrict__ xtl) {
    __shared__ float tile[32][33];
    const int n0 = blockIdx.x * 32;
    const int d0 = blockIdx.y * 32;
    const int tx = threadIdx.x, ty = threadIdx.y;   // 32 x 8
    #pragma unroll
    for (int k = 0; k < 4; ++k)
        tile[ty + 8 * k][tx] = x[(size_t)(d0 + ty + 8 * k) * N_SAMP + n0 + tx];
    __syncthreads();
    #pragma unroll
    for (int k = 0; k < 4; ++k) {
        float v = tile[tx][ty + 8 * k];
        __nv_bfloat16 h, l;
        split_f32(v, h, l);
        size_t o = (size_t)(n0 + ty + 8 * k) * D_FEAT + d0 + tx;
        xth[o] = h;
        xtl[o] = l;
    }
}

// ---------------------------------------------------------------- HMMA GEMM
// C[M,N] = (Ahi+Alo)[M,K] * (Bhi+Blo)[N,K]^T via hi*hi + hi*lo + lo*hi.
// CTA 128x128, 512 threads (16 warps, 32x32 warp tile), K_TILE=32,
// 3-stage cp.async ring. Smem row stride 80B (40 bf16) -> conflict-free ldmatrix.
// EPI=0: fp32 out. EPI=1: bf16 hi/lo split out.
#define STG_BYTES 40960          // 4 arrays * 128 rows * 80B
#define ARR_BYTES 10240

template <int EPI>
__global__ void __launch_bounds__(512, 1)
gemm_hmma(const __nv_bfloat16* __restrict__ Ahi, const __nv_bfloat16* __restrict__ Alo,
          const __nv_bfloat16* __restrict__ Bhi, const __nv_bfloat16* __restrict__ Blo,
          float* __restrict__ Cf,
          __nv_bfloat16* __restrict__ Chi, __nv_bfloat16* __restrict__ Clo,
          int N, int K) {
    extern __shared__ char smem[];
    const uint32_t sb = smem_u32(smem);

    const int tid  = threadIdx.x;
    const int wid  = tid >> 5;
    const int lane = tid & 31;
    const int wm   = wid & 3;          // 0..3 -> 32-row slab
    const int wn   = wid >> 2;         // 0..3 -> 32-col slab
    const int m0   = blockIdx.x * 128;
    const int n0   = blockIdx.y * 128;

    // cp.async loader mapping: one uint4 per thread per array per stage
    const int lrow  = tid >> 2;                 // 0..127
    const int lcolv = tid & 3;                  // 0..3 -> 8 bf16 each
    const size_t gA = (size_t)(m0 + lrow) * K + lcolv * 8;
    const size_t gB = (size_t)(n0 + lrow) * K + lcolv * 8;
    const uint32_t soff = lrow * 80 + lcolv * 16;

    // ldmatrix per-lane address components
    const int quad = lane >> 3, l8 = lane & 7;
    const int a_row  = wm * 32 + (quad & 1) * 8 + l8;
    const int a_colq = (quad >> 1) * 8;
    const int b_row  = wn * 32 + (quad >> 1) * 8 + l8;
    const int b_colq = (quad & 1) * 8;

    float acc[2][4][4];
    #pragma unroll
    for (int i = 0; i < 2; ++i)
        #pragma unroll
        for (int j = 0; j < 4; ++j)
            #pragma unroll
            for (int e = 0; e < 4; ++e) acc[i][j][e] = 0.f;

    const int ntiles = K / 32;

    // ---- stage load: 4 arrays, 1 uint4/thread each
    auto load_stage = [&](int t) {
        const uint32_t d = sb + (t % 3) * STG_BYTES + soff;
        const size_t k = (size_t)t * 32;
        cpasync16(d,                 Ahi + gA + k);
        cpasync16(d + ARR_BYTES,     Alo + gA + k);
        cpasync16(d + 2 * ARR_BYTES, Bhi + gB + k);
        cpasync16(d + 3 * ARR_BYTES, Blo + gB + k);
        cp_commit();
    };

    load_stage(0);
    load_stage(1);

    for (int s = 0; s < ntiles; ++s) {
        cp_wait1();
        __syncthreads();
        if (s + 2 < ntiles) load_stage(s + 2);

        const uint32_t st = sb + (s % 3) * STG_BYTES;
        #pragma unroll
        for (int h = 0; h < 2; ++h) {
            const int k0 = h * 16;
            uint32_t Ah[2][4], Al[2][4], Bh[2][4], Bl[2][4];
            #pragma unroll
            for (int i = 0; i < 2; ++i) {
                const uint32_t ao = (a_row + i * 16) * 80 + (k0 + a_colq) * 2;
                ldsm4(Ah[i], st + ao);
                ldsm4(Al[i], st + ARR_BYTES + ao);
            }
            #pragma unroll
            for (int j = 0; j < 2; ++j) {   // each x4 covers two n8 tiles
                const uint32_t bo = (b_row + j * 16) * 80 + (k0 + b_colq) * 2;
                ldsm4(Bh[j], st + 2 * ARR_BYTES + bo);
                ldsm4(Bl[j], st + 3 * ARR_BYTES + bo);
            }
            #pragma unroll
            for (int i = 0; i < 2; ++i)
                #pragma unroll
                for (int j = 0; j < 4; ++j) {
                    const uint32_t* bh = &Bh[j >> 1][(j & 1) * 2];
                    const uint32_t* bl = &Bl[j >> 1][(j & 1) * 2];
                    mma16816(acc[i][j], Ah[i], bh);
                    mma16816(acc[i][j], Ah[i], bl);
                    mma16816(acc[i][j], Al[i], bh);
                }
        }
    }

    // ---- epilogue
    const int r_base = m0 + wm * 32 + (lane >> 2);
    const int c_base = n0 + wn * 32 + (lane & 3) * 2;
    #pragma unroll
    for (int i = 0; i < 2; ++i) {
        #pragma unroll
        for (int j = 0; j < 4; ++j) {
            const int r0 = r_base + i * 16;
            const int c  = c_base + j * 8;
            if (EPI == 0) {
                *reinterpret_cast<float2*>(Cf + (size_t)r0 * N + c) =
                    make_float2(acc[i][j][0], acc[i][j][1]);
                *reinterpret_cast<float2*>(Cf + (size_t)(r0 + 8) * N + c) =
                    make_float2(acc[i][j][2], acc[i][j][3]);
            } else {
                __nv_bfloat16 h0, l0, h1, l1;
                split_f32(acc[i][j][0], h0, l0);
                split_f32(acc[i][j][1], h1, l1);
                *reinterpret_cast<__nv_bfloat162*>(Chi + (size_t)r0 * N + c) = __halves2bfloat162(h0, h1);
                *reinterpret_cast<__nv_bfloat162*>(Clo + (size_t)r0 * N + c) = __halves2bfloat162(l0, l1);
                split_f32(acc[i][j][2], h0, l0);
                split_f32(acc[i][j][3], h1, l1);
                *reinterpret_cast<__nv_bfloat162*>(Chi + (size_t)(r0 + 8) * N + c) = __halves2bfloat162(h0, h1);
                *reinterpret_cast<__nv_bfloat162*>(Clo + (size_t)(r0 + 8) * N + c) = __halves2bfloat162(l0, l1);
            }
        }
    }
}

// ---------------------------------------------------------------- launch
extern "C" void kernel_launch(void* const* d_in, const int* in_sizes, int n_in,
                              void* d_out, int out_size) {
    (void)n_in; (void)out_size;

    const float* x;
    const float* Psi;
    if (in_sizes[0] == D_FEAT * N_SAMP) {
        x   = (const float*)d_in[0];
        Psi = (const float*)d_in[1];
    } else {
        x   = (const float*)d_in[1];
        Psi = (const float*)d_in[0];
    }
    float* out = (float*)d_out;

    float *mu;
    __nv_bfloat16 *psi_hi, *psi_lo, *x_hi, *x_lo, *xt_hi, *xt_lo, *tmp_hi, *tmp_lo;
    cudaGetSymbolAddress((void**)&mu,     g_mu);
    cudaGetSymbolAddress((void**)&psi_hi, g_psi_hi);
    cudaGetSymbolAddress((void**)&psi_lo, g_psi_lo);
    cudaGetSymbolAddress((void**)&x_hi,   g_x_hi);
    cudaGetSymbolAddress((void**)&x_lo,   g_x_lo);
    cudaGetSymbolAddress((void**)&xt_hi,  g_xt_hi);
    cudaGetSymbolAddress((void**)&xt_lo,  g_xt_lo);
    cudaGetSymbolAddress((void**)&tmp_hi, g_tmp_hi);
    cudaGetSymbolAddress((void**)&tmp_lo, g_tmp_lo);

    const int SMEM_BYTES = 3 * STG_BYTES;   // 122880
    cudaFuncSetAttribute(gemm_hmma<0>, cudaFuncAttributeMaxDynamicSharedMemorySize, SMEM_BYTES);
    cudaFuncSetAttribute(gemm_hmma<1>, cudaFuncAttributeMaxDynamicSharedMemorySize, SMEM_BYTES);

    // 1) row means
    rowmean_kernel<<<OUT_D, 256>>>(Psi, mu);

    // 2) conversions
    center_split_kernel<<<(OUT_D * (N_SAMP / 4)) / 256, 256>>>(Psi, mu, psi_hi, psi_lo);
    split_kernel<<<(D_FEAT * (N_SAMP / 4)) / 256, 256>>>(x, x_hi, x_lo);
    {
        dim3 grid(N_SAMP / 32, D_FEAT / 32);
        transpose_split_kernel<<<grid, dim3(32, 8)>>>(x, xt_hi, xt_lo);
    }

    // 3) GEMM1: tmp[o,d] = Psi_c[o,:] . x[d,:]   (M=2048, N=4096, K=8192)
    {
        dim3 grid(OUT_D / 128, D_FEAT / 128);   // (16, 32)
        gemm_hmma<1><<<grid, 512, SMEM_BYTES>>>(
            psi_hi, psi_lo, x_hi, x_lo, nullptr, tmp_hi, tmp_lo, D_FEAT, N_SAMP);
    }

    // 4) GEMM2: out[o,n] = tmp[o,:] . xt[n,:]    (M=2048, N=8192, K=4096)
    {
        dim3 grid(OUT_D / 128, N_SAMP / 128);   // (16, 64)
        gemm_hmma<0><<<grid, 512, SMEM_BYTES>>>(
            tmp_hi, tmp_lo, xt_hi, xt_lo, out, nullptr, nullptr, N_SAMP, D_FEAT);
    }
}

// round 4
// speedup vs baseline: 3.1808x; 1.2895x over previous
#include <cuda_runtime.h>
#include <cuda_bf16.h>
#include <cstdint>

// ---------------------------------------------------------------- shapes
#define D_FEAT 4096
#define N_SAMP 8192
#define OUT_D  2048

// ---------------------------------------------------------------- scratch
__device__ __nv_bfloat16 g_psi_hi[(size_t)OUT_D * N_SAMP];
__device__ __nv_bfloat16 g_psi_lo[(size_t)OUT_D * N_SAMP];
__device__ __nv_bfloat16 g_x_hi[(size_t)D_FEAT * N_SAMP];
__device__ __nv_bfloat16 g_x_lo[(size_t)D_FEAT * N_SAMP];
__device__ __nv_bfloat16 g_xt_hi[(size_t)N_SAMP * D_FEAT];
__device__ __nv_bfloat16 g_xt_lo[(size_t)N_SAMP * D_FEAT];
__device__ __nv_bfloat16 g_tmp_hi[(size_t)OUT_D * D_FEAT];
__device__ __nv_bfloat16 g_tmp_lo[(size_t)OUT_D * D_FEAT];

// ---------------------------------------------------------------- helpers
__device__ __forceinline__ uint32_t smem_u32(const void* p) {
    uint32_t a;
    asm("{ .reg .u64 t; cvta.to.shared.u64 t, %1; cvt.u32.u64 %0, t; }" : "=r"(a) : "l"(p));
    return a;
}
__device__ __forceinline__ void cpasync16(uint32_t s, const void* g) {
    asm volatile("cp.async.cg.shared.global [%0], [%1], 16;" :: "r"(s), "l"(g));
}
__device__ __forceinline__ void cp_commit() {
    asm volatile("cp.async.commit_group;" ::: "memory");
}
__device__ __forceinline__ void cp_wait1() {
    asm volatile("cp.async.wait_group 1;" ::: "memory");
}
__device__ __forceinline__ void ldsm4(uint32_t* r, uint32_t addr) {
    asm volatile("ldmatrix.sync.aligned.m8n8.x4.shared.b16 {%0,%1,%2,%3}, [%4];"
                 : "=r"(r[0]), "=r"(r[1]), "=r"(r[2]), "=r"(r[3]) : "r"(addr));
}
__device__ __forceinline__ void mma16816(float* c, const uint32_t* a, const uint32_t* b) {
    asm volatile("mma.sync.aligned.m16n8k16.row.col.f32.bf16.bf16.f32 "
                 "{%0,%1,%2,%3}, {%4,%5,%6,%7}, {%8,%9}, {%0,%1,%2,%3};"
                 : "+f"(c[0]), "+f"(c[1]), "+f"(c[2]), "+f"(c[3])
                 : "r"(a[0]), "r"(a[1]), "r"(a[2]), "r"(a[3]), "r"(b[0]), "r"(b[1]));
}
__device__ __forceinline__ void split_f32(float v, __nv_bfloat16& h, __nv_bfloat16& l) {
    h = __float2bfloat16(v);
    l = __float2bfloat16(v - __bfloat162float(h));
}
// SW64 swizzle for 64-byte rows (conflict-free ldmatrix / cp.async)
__device__ __forceinline__ uint32_t sw64(uint32_t off) {
    return off ^ ((off >> 3) & 0x30);
}

// ---------------------------------------------------- Psi: mean+center+split
__global__ void mean_center_split_kernel(const float* __restrict__ Psi,
                                         __nv_bfloat16* __restrict__ hi,
                                         __nv_bfloat16* __restrict__ lo) {
    const int row = blockIdx.x;
    const float4* p = reinterpret_cast<const float4*>(Psi) + (size_t)row * (N_SAMP / 4);
    float4 v[8];
    float s = 0.f;
    #pragma unroll
    for (int q = 0; q < 8; ++q) {
        v[q] = p[q * 256 + threadIdx.x];
        s += (v[q].x + v[q].y) + (v[q].z + v[q].w);
    }
    __shared__ float red[256];
    red[threadIdx.x] = s;
    __syncthreads();
    #pragma unroll
    for (int off = 128; off > 0; off >>= 1) {
        if (threadIdx.x < off) red[threadIdx.x] += red[threadIdx.x + off];
        __syncthreads();
    }
    const float m = red[0] * (1.0f / N_SAMP);
    ushort4* hp = reinterpret_cast<ushort4*>(hi) + (size_t)row * (N_SAMP / 4);
    ushort4* lp = reinterpret_cast<ushort4*>(lo) + (size_t)row * (N_SAMP / 4);
    #pragma unroll
    for (int q = 0; q < 8; ++q) {
        float4 w = v[q];
        w.x -= m; w.y -= m; w.z -= m; w.w -= m;
        __nv_bfloat16 h0, l0, h1, l1, h2, l2, h3, l3;
        split_f32(w.x, h0, l0); split_f32(w.y, h1, l1);
        split_f32(w.z, h2, l2); split_f32(w.w, h3, l3);
        hp[q * 256 + threadIdx.x] = make_ushort4(
            __bfloat16_as_ushort(h0), __bfloat16_as_ushort(h1),
            __bfloat16_as_ushort(h2), __bfloat16_as_ushort(h3));
        lp[q * 256 + threadIdx.x] = make_ushort4(
            __bfloat16_as_ushort(l0), __bfloat16_as_ushort(l1),
            __bfloat16_as_ushort(l2), __bfloat16_as_ushort(l3));
    }
}

// ---------------------------------------------------- x: split + transpose-split
__global__ void x_split_all_kernel(const float* __restrict__ x,
                                   __nv_bfloat16* __restrict__ xh, __nv_bfloat16* __restrict__ xl,
                                   __nv_bfloat16* __restrict__ xth, __nv_bfloat16* __restrict__ xtl) {
    __shared__ float tile[32][33];
    const int n0 = blockIdx.x * 32;
    const int d0 = blockIdx.y * 32;
    const int tx = threadIdx.x, ty = threadIdx.y;   // 32 x 8
    #pragma unroll
    for (int k = 0; k < 4; ++k) {
        const int d = d0 + ty + 8 * k;
        const size_t o = (size_t)d * N_SAMP + n0 + tx;
        float v = x[o];
        tile[ty + 8 * k][tx] = v;
        __nv_bfloat16 h, l;
        split_f32(v, h, l);
        xh[o] = h;
        xl[o] = l;
    }
    __syncthreads();
    #pragma unroll
    for (int k = 0; k < 4; ++k) {
        float v = tile[tx][ty + 8 * k];
        __nv_bfloat16 h, l;
        split_f32(v, h, l);
        size_t o = (size_t)(n0 + ty + 8 * k) * D_FEAT + d0 + tx;
        xth[o] = h;
        xtl[o] = l;
    }
}

// ---------------------------------------------------------------- HMMA GEMM
// C[M,N] = (Ahi+Alo)[M,K]*(Bhi+Blo)[N,K]^T via hi*hi + hi*lo + lo*hi.
// CTA 128x128, 256 threads (8 warps, warp tile 32x64), K_TILE=32.
// SW64-swizzled 64B rows, 3-stage cp.async ring (32KB/stage, 96KB total),
// 2 CTAs/SM. EPI=0: fp32 out. EPI=1: bf16 hi/lo split out.
#define STG_BYTES 32768
#define AH_OFF 0
#define AL_OFF 8192
#define BH_OFF 16384
#define BL_OFF 24576

template <int EPI>
__global__ void __launch_bounds__(256, 2)
gemm_hmma(const __nv_bfloat16* __restrict__ Ahi, const __nv_bfloat16* __restrict__ Alo,
          const __nv_bfloat16* __restrict__ Bhi, const __nv_bfloat16* __restrict__ Blo,
          float* __restrict__ Cf,
          __nv_bfloat16* __restrict__ Chi, __nv_bfloat16* __restrict__ Clo,
          int N, int K) {
    extern __shared__ char smem[];
    const uint32_t sb = smem_u32(smem);

    const int tid  = threadIdx.x;
    const int wid  = tid >> 5;
    const int lane = tid & 31;
    const int wm   = wid & 3;          // 0..3 -> 32-row slab
    const int wn   = wid >> 2;         // 0..1 -> 64-col slab
    const int m0   = blockIdx.x * 128;
    const int n0   = blockIdx.y * 128;

    // loader: 2 chunks per array per thread (512 chunks of 16B per 128x32 array)
    uint32_t soff[2];
    size_t gA[2], gB[2];
    #pragma unroll
    for (int q = 0; q < 2; ++q) {
        const int id  = q * 256 + tid;
        const int r   = id >> 2;
        const int sg  = id & 3;
        soff[q] = sw64((uint32_t)(r * 64 + sg * 16));
        gA[q]   = (size_t)(m0 + r) * K + sg * 8;
        gB[q]   = (size_t)(n0 + r) * K + sg * 8;
    }

    auto load_stage = [&](int t) {
        const uint32_t base = sb + (t % 3) * STG_BYTES;
        const size_t k = (size_t)t * 32;
        #pragma unroll
        for (int q = 0; q < 2; ++q) {
            cpasync16(base + AH_OFF + soff[q], Ahi + gA[q] + k);
            cpasync16(base + AL_OFF + soff[q], Alo + gA[q] + k);
            cpasync16(base + BH_OFF + soff[q], Bhi + gB[q] + k);
            cpasync16(base + BL_OFF + soff[q], Blo + gB[q] + k);
        }
        cp_commit();
    };

    // ldmatrix per-lane row/col components
    const int quad = lane >> 3, l8 = lane & 7;
    const int a_row  = wm * 32 + (quad & 1) * 8 + l8;   // + i*16
    const int a_colq = (quad >> 1) * 8;                 // + k0
    const int b_row  = wn * 64 + (quad >> 1) * 8 + l8;  // + j*16
    const int b_colq = (quad & 1) * 8;                  // + k0

    float acc[2][8][4];
    #pragma unroll
    for (int i = 0; i < 2; ++i)
        #pragma unroll
        for (int j = 0; j < 8; ++j)
            #pragma unroll
            for (int e = 0; e < 4; ++e) acc[i][j][e] = 0.f;

    const int ntiles = K / 32;
    load_stage(0);
    load_stage(1);

    for (int s = 0; s < ntiles; ++s) {
        cp_wait1();
        __syncthreads();
        if (s + 2 < ntiles) load_stage(s + 2);

        const uint32_t st = sb + (s % 3) * STG_BYTES;
        #pragma unroll
        for (int h = 0; h < 2; ++h) {
            const int k0 = h * 16;
            uint32_t Ah[2][4], Al[2][4];
            #pragma unroll
            for (int i = 0; i < 2; ++i) {
                const uint32_t ao = sw64((uint32_t)((a_row + i * 16) * 64 + (k0 + a_colq) * 2));
                ldsm4(Ah[i], st + AH_OFF + ao);
                ldsm4(Al[i], st + AL_OFF + ao);
            }
            #pragma unroll
            for (int jj = 0; jj < 2; ++jj) {      // two n32 halves -> bounded B-frag liveness
                uint32_t Bh[2][4], Bl[2][4];
                #pragma unroll
                for (int j = 0; j < 2; ++j) {     // each x4 covers n16 (two n8 tiles)
                    const uint32_t bo = sw64((uint32_t)((b_row + (jj * 2 + j) * 16) * 64 + (k0 + b_colq) * 2));
                    ldsm4(Bh[j], st + BH_OFF + bo);
                    ldsm4(Bl[j], st + BL_OFF + bo);
                }
                #pragma unroll
                for (int i = 0; i < 2; ++i)
                    #pragma unroll
                    for (int j = 0; j < 4; ++j) {
                        float* c = acc[i][jj * 4 + j];
                        const uint32_t* bh = &Bh[j >> 1][(j & 1) * 2];
                        const uint32_t* bl = &Bl[j >> 1][(j & 1) * 2];
                        mma16816(c, Ah[i], bh);
                        mma16816(c, Ah[i], bl);
                        mma16816(c, Al[i], bh);
                    }
            }
        }
    }

    // ---- epilogue
    const int r_base = m0 + wm * 32 + (lane >> 2);
    const int c_base = n0 + wn * 64 + (lane & 3) * 2;
    #pragma unroll
    for (int i = 0; i < 2; ++i) {
        #pragma unroll
        for (int j = 0; j < 8; ++j) {
            const int r0 = r_base + i * 16;
            const int c  = c_base + j * 8;
            if (EPI == 0) {
                *reinterpret_cast<float2*>(Cf + (size_t)r0 * N + c) =
                    make_float2(acc[i][j][0], acc[i][j][1]);
                *reinterpret_cast<float2*>(Cf + (size_t)(r0 + 8) * N + c) =
                    make_float2(acc[i][j][2], acc[i][j][3]);
            } else {
                __nv_bfloat16 h0, l0, h1, l1;
                split_f32(acc[i][j][0], h0, l0);
                split_f32(acc[i][j][1], h1, l1);
                *reinterpret_cast<__nv_bfloat162*>(Chi + (size_t)r0 * N + c) = __halves2bfloat162(h0, h1);
                *reinterpret_cast<__nv_bfloat162*>(Clo + (size_t)r0 * N + c) = __halves2bfloat162(l0, l1);
                split_f32(acc[i][j][2], h0, l0);
                split_f32(acc[i][j][3], h1, l1);
                *reinterpret_cast<__nv_bfloat162*>(Chi + (size_t)(r0 + 8) * N + c) = __halves2bfloat162(h0, h1);
                *reinterpret_cast<__nv_bfloat162*>(Clo + (size_t)(r0 + 8) * N + c) = __halves2bfloat162(l0, l1);
            }
        }
    }
}

// ---------------------------------------------------------------- launch
extern "C" void kernel_launch(void* const* d_in, const int* in_sizes, int n_in,
                              void* d_out, int out_size) {
    (void)n_in; (void)out_size;

    const float* x;
    const float* Psi;
    if (in_sizes[0] == D_FEAT * N_SAMP) {
        x   = (const float*)d_in[0];
        Psi = (const float*)d_in[1];
    } else {
        x   = (const float*)d_in[1];
        Psi = (const float*)d_in[0];
    }
    float* out = (float*)d_out;

    __nv_bfloat16 *psi_hi, *psi_lo, *x_hi, *x_lo, *xt_hi, *xt_lo, *tmp_hi, *tmp_lo;
    cudaGetSymbolAddress((void**)&psi_hi, g_psi_hi);
    cudaGetSymbolAddress((void**)&psi_lo, g_psi_lo);
    cudaGetSymbolAddress((void**)&x_hi,   g_x_hi);
    cudaGetSymbolAddress((void**)&x_lo,   g_x_lo);
    cudaGetSymbolAddress((void**)&xt_hi,  g_xt_hi);
    cudaGetSymbolAddress((void**)&xt_lo,  g_xt_lo);
    cudaGetSymbolAddress((void**)&tmp_hi, g_tmp_hi);
    cudaGetSymbolAddress((void**)&tmp_lo, g_tmp_lo);

    const int SMEM_BYTES = 3 * STG_BYTES;   // 98304
    cudaFuncSetAttribute(gemm_hmma<0>, cudaFuncAttributeMaxDynamicSharedMemorySize, SMEM_BYTES);
    cudaFuncSetAttribute(gemm_hmma<1>, cudaFuncAttributeMaxDynamicSharedMemorySize, SMEM_BYTES);

    // 1) Psi: mean + center + bf16 split (single pass)
    mean_center_split_kernel<<<OUT_D, 256>>>(Psi, psi_hi, psi_lo);

    // 2) x: split (both layouts, single read pass)
    {
        dim3 grid(N_SAMP / 32, D_FEAT / 32);
        x_split_all_kernel<<<grid, dim3(32, 8)>>>(x, x_hi, x_lo, xt_hi, xt_lo);
    }

    // 3) GEMM1: tmp[o,d] = Psi_c[o,:] . x[d,:]   (M=2048, N=4096, K=8192)
    {
        dim3 grid(OUT_D / 128, D_FEAT / 128);   // (16, 32)
        gemm_hmma<1><<<grid, 256, SMEM_BYTES>>>(
            psi_hi, psi_lo, x_hi, x_lo, nullptr, tmp_hi, tmp_lo, D_FEAT, N_SAMP);
    }

    // 4) GEMM2: out[o,n] = tmp[o,:] . xt[n,:]    (M=2048, N=8192, K=4096)
    {
        dim3 grid(OUT_D / 128, N_SAMP / 128);   // (16, 64)
        gemm_hmma<0><<<grid, 256, SMEM_BYTES>>>(
            tmp_hi, tmp_lo, xt_hi, xt_lo, out, nullptr, nullptr, N_SAMP, D_FEAT);
    }
}

// round 5
// speedup vs baseline: 3.2608x; 1.0251x over previous
#include <cuda_runtime.h>
#include <cuda_bf16.h>
#include <cstdint>

// ---------------------------------------------------------------- shapes
#define D_FEAT 4096
#define N_SAMP 8192
#define OUT_D  2048

// ---------------------------------------------------------------- scratch
__device__ __nv_bfloat16 g_psi_hi[(size_t)OUT_D * N_SAMP];
__device__ __nv_bfloat16 g_psi_lo[(size_t)OUT_D * N_SAMP];
__device__ __nv_bfloat16 g_x_hi[(size_t)D_FEAT * N_SAMP];
__device__ __nv_bfloat16 g_x_lo[(size_t)D_FEAT * N_SAMP];
__device__ __nv_bfloat16 g_xt_hi[(size_t)N_SAMP * D_FEAT];
__device__ __nv_bfloat16 g_xt_lo[(size_t)N_SAMP * D_FEAT];
__device__ __nv_bfloat16 g_tmp_hi[(size_t)OUT_D * D_FEAT];
__device__ __nv_bfloat16 g_tmp_lo[(size_t)OUT_D * D_FEAT];
__device__ float g_part1[(size_t)4 * OUT_D * D_FEAT];   // 4 x 8.4M  (128MB)
__device__ float g_part2[(size_t)2 * OUT_D * N_SAMP];   // 2 x 16.8M (134MB)

// ---------------------------------------------------------------- helpers
__device__ __forceinline__ uint32_t smem_u32(const void* p) {
    uint32_t a;
    asm("{ .reg .u64 t; cvta.to.shared.u64 t, %1; cvt.u32.u64 %0, t; }" : "=r"(a) : "l"(p));
    return a;
}
__device__ __forceinline__ void cpasync16(uint32_t s, const void* g) {
    asm volatile("cp.async.cg.shared.global [%0], [%1], 16;" :: "r"(s), "l"(g));
}
__device__ __forceinline__ void cp_commit() {
    asm volatile("cp.async.commit_group;" ::: "memory");
}
__device__ __forceinline__ void cp_wait1() {
    asm volatile("cp.async.wait_group 1;" ::: "memory");
}
__device__ __forceinline__ void ldsm4(uint32_t* r, uint32_t addr) {
    asm volatile("ldmatrix.sync.aligned.m8n8.x4.shared.b16 {%0,%1,%2,%3}, [%4];"
                 : "=r"(r[0]), "=r"(r[1]), "=r"(r[2]), "=r"(r[3]) : "r"(addr));
}
__device__ __forceinline__ void mma16816(float* c, const uint32_t* a, const uint32_t* b) {
    asm volatile("mma.sync.aligned.m16n8k16.row.col.f32.bf16.bf16.f32 "
                 "{%0,%1,%2,%3}, {%4,%5,%6,%7}, {%8,%9}, {%0,%1,%2,%3};"
                 : "+f"(c[0]), "+f"(c[1]), "+f"(c[2]), "+f"(c[3])
                 : "r"(a[0]), "r"(a[1]), "r"(a[2]), "r"(a[3]), "r"(b[0]), "r"(b[1]));
}
__device__ __forceinline__ void split_f32(float v, __nv_bfloat16& h, __nv_bfloat16& l) {
    h = __float2bfloat16(v);
    l = __float2bfloat16(v - __bfloat162float(h));
}
__device__ __forceinline__ uint32_t sw64(uint32_t off) {
    return off ^ ((off >> 3) & 0x30);
}

// ---------------------------------------------------- Psi: mean+center+split
__global__ void mean_center_split_kernel(const float* __restrict__ Psi,
                                         __nv_bfloat16* __restrict__ hi,
                                         __nv_bfloat16* __restrict__ lo) {
    const int row = blockIdx.x;
    const float4* p = reinterpret_cast<const float4*>(Psi) + (size_t)row * (N_SAMP / 4);
    float4 v[8];
    float s = 0.f;
    #pragma unroll
    for (int q = 0; q < 8; ++q) {
        v[q] = p[q * 256 + threadIdx.x];
        s += (v[q].x + v[q].y) + (v[q].z + v[q].w);
    }
    __shared__ float red[256];
    red[threadIdx.x] = s;
    __syncthreads();
    #pragma unroll
    for (int off = 128; off > 0; off >>= 1) {
        if (threadIdx.x < off) red[threadIdx.x] += red[threadIdx.x + off];
        __syncthreads();
    }
    const float m = red[0] * (1.0f / N_SAMP);
    ushort4* hp = reinterpret_cast<ushort4*>(hi) + (size_t)row * (N_SAMP / 4);
    ushort4* lp = reinterpret_cast<ushort4*>(lo) + (size_t)row * (N_SAMP / 4);
    #pragma unroll
    for (int q = 0; q < 8; ++q) {
        float4 w = v[q];
        w.x -= m; w.y -= m; w.z -= m; w.w -= m;
        __nv_bfloat16 h0, l0, h1, l1, h2, l2, h3, l3;
        split_f32(w.x, h0, l0); split_f32(w.y, h1, l1);
        split_f32(w.z, h2, l2); split_f32(w.w, h3, l3);
        hp[q * 256 + threadIdx.x] = make_ushort4(
            __bfloat16_as_ushort(h0), __bfloat16_as_ushort(h1),
            __bfloat16_as_ushort(h2), __bfloat16_as_ushort(h3));
        lp[q * 256 + threadIdx.x] = make_ushort4(
            __bfloat16_as_ushort(l0), __bfloat16_as_ushort(l1),
            __bfloat16_as_ushort(l2), __bfloat16_as_ushort(l3));
    }
}

// ---------------------------------------------------- x: split + transpose-split
__global__ void x_split_all_kernel(const float* __restrict__ x,
                                   __nv_bfloat16* __restrict__ xh, __nv_bfloat16* __restrict__ xl,
                                   __nv_bfloat16* __restrict__ xth, __nv_bfloat16* __restrict__ xtl) {
    __shared__ float tile[32][33];
    const int n0 = blockIdx.x * 32;
    const int d0 = blockIdx.y * 32;
    const int tx = threadIdx.x, ty = threadIdx.y;   // 32 x 8
    #pragma unroll
    for (int k = 0; k < 4; ++k) {
        const int d = d0 + ty + 8 * k;
        const size_t o = (size_t)d * N_SAMP + n0 + tx;
        float v = x[o];
        tile[ty + 8 * k][tx] = v;
        __nv_bfloat16 h, l;
        split_f32(v, h, l);
        xh[o] = h;
        xl[o] = l;
    }
    __syncthreads();
    #pragma unroll
    for (int k = 0; k < 4; ++k) {
        float v = tile[tx][ty + 8 * k];
        __nv_bfloat16 h, l;
        split_f32(v, h, l);
        size_t o = (size_t)(n0 + ty + 8 * k) * D_FEAT + d0 + tx;
        xth[o] = h;
        xtl[o] = l;
    }
}

// ---------------------------------------------------------------- HMMA GEMM (split-K)
// Cpart[z] [M,N] = (Ahi+Alo)[M, kz:kz+KLEN] * (Bhi+Blo)[N, kz:kz+KLEN]^T,
// kz = blockIdx.z * KLEN, via hi*hi + hi*lo + lo*hi. Plain fp32 partial stores.
// CTA 128x128, 256 threads (8 warps, warp tile 32x64), K_TILE=32,
// SW64 64B rows, 3-stage cp.async ring (96KB), 2 CTAs/SM.
#define STG_BYTES 32768
#define AH_OFF 0
#define AL_OFF 8192
#define BH_OFF 16384
#define BL_OFF 24576

__global__ void __launch_bounds__(256, 2)
gemm_hmma(const __nv_bfloat16* __restrict__ Ahi, const __nv_bfloat16* __restrict__ Alo,
          const __nv_bfloat16* __restrict__ Bhi, const __nv_bfloat16* __restrict__ Blo,
          float* __restrict__ Cpart,
          int N, int K, int klen) {
    extern __shared__ char smem[];
    const uint32_t sb = smem_u32(smem);

    const int tid  = threadIdx.x;
    const int wid  = tid >> 5;
    const int lane = tid & 31;
    const int wm   = wid & 3;
    const int wn   = wid >> 2;
    const int m0   = blockIdx.x * 128;
    const int n0   = blockIdx.y * 128;
    const int kz   = blockIdx.z * klen;
    float* C = Cpart + (size_t)blockIdx.z * ((size_t)gridDim.x * 128) * N;

    uint32_t soff[2];
    size_t gA[2], gB[2];
    #pragma unroll
    for (int q = 0; q < 2; ++q) {
        const int id  = q * 256 + tid;
        const int r   = id >> 2;
        const int sg  = id & 3;
        soff[q] = sw64((uint32_t)(r * 64 + sg * 16));
        gA[q]   = (size_t)(m0 + r) * K + kz + sg * 8;
        gB[q]   = (size_t)(n0 + r) * K + kz + sg * 8;
    }

    auto load_stage = [&](int t) {
        const uint32_t base = sb + (t % 3) * STG_BYTES;
        const size_t k = (size_t)t * 32;
        #pragma unroll
        for (int q = 0; q < 2; ++q) {
            cpasync16(base + AH_OFF + soff[q], Ahi + gA[q] + k);
            cpasync16(base + AL_OFF + soff[q], Alo + gA[q] + k);
            cpasync16(base + BH_OFF + soff[q], Bhi + gB[q] + k);
            cpasync16(base + BL_OFF + soff[q], Blo + gB[q] + k);
        }
        cp_commit();
    };

    const int quad = lane >> 3, l8 = lane & 7;
    const int a_row  = wm * 32 + (quad & 1) * 8 + l8;
    const int a_colq = (quad >> 1) * 8;
    const int b_row  = wn * 64 + (quad >> 1) * 8 + l8;
    const int b_colq = (quad & 1) * 8;

    float acc[2][8][4];
    #pragma unroll
    for (int i = 0; i < 2; ++i)
        #pragma unroll
        for (int j = 0; j < 8; ++j)
            #pragma unroll
            for (int e = 0; e < 4; ++e) acc[i][j][e] = 0.f;

    const int ntiles = klen / 32;
    load_stage(0);
    load_stage(1);

    for (int s = 0; s < ntiles; ++s) {
        cp_wait1();
        __syncthreads();
        if (s + 2 < ntiles) load_stage(s + 2);

        const uint32_t st = sb + (s % 3) * STG_BYTES;
        #pragma unroll
        for (int h = 0; h < 2; ++h) {
            const int k0 = h * 16;
            uint32_t Ah[2][4], Al[2][4];
            #pragma unroll
            for (int i = 0; i < 2; ++i) {
                const uint32_t ao = sw64((uint32_t)((a_row + i * 16) * 64 + (k0 + a_colq) * 2));
                ldsm4(Ah[i], st + AH_OFF + ao);
                ldsm4(Al[i], st + AL_OFF + ao);
            }
            #pragma unroll
            for (int jj = 0; jj < 2; ++jj) {
                uint32_t Bh[2][4], Bl[2][4];
                #pragma unroll
                for (int j = 0; j < 2; ++j) {
                    const uint32_t bo = sw64((uint32_t)((b_row + (jj * 2 + j) * 16) * 64 + (k0 + b_colq) * 2));
                    ldsm4(Bh[j], st + BH_OFF + bo);
                    ldsm4(Bl[j], st + BL_OFF + bo);
                }
                #pragma unroll
                for (int i = 0; i < 2; ++i)
                    #pragma unroll
                    for (int j = 0; j < 4; ++j) {
                        float* c = acc[i][jj * 4 + j];
                        const uint32_t* bh = &Bh[j >> 1][(j & 1) * 2];
                        const uint32_t* bl = &Bl[j >> 1][(j & 1) * 2];
                        mma16816(c, Ah[i], bh);
                        mma16816(c, Ah[i], bl);
                        mma16816(c, Al[i], bh);
                    }
            }
        }
    }

    // ---- epilogue: plain fp32 partial stores
    const int r_base = m0 + wm * 32 + (lane >> 2);
    const int c_base = n0 + wn * 64 + (lane & 3) * 2;
    #pragma unroll
    for (int i = 0; i < 2; ++i) {
        #pragma unroll
        for (int j = 0; j < 8; ++j) {
            const int r0 = r_base + i * 16;
            const int c  = c_base + j * 8;
            *reinterpret_cast<float2*>(C + (size_t)r0 * N + c) =
                make_float2(acc[i][j][0], acc[i][j][1]);
            *reinterpret_cast<float2*>(C + (size_t)(r0 + 8) * N + c) =
                make_float2(acc[i][j][2], acc[i][j][3]);
        }
    }
}

// ---------------------------------------------- reduce 4 partials -> bf16 hi/lo
__global__ void reduce4_split_kernel(const float* __restrict__ p,
                                     __nv_bfloat16* __restrict__ hi,
                                     __nv_bfloat16* __restrict__ lo) {
    const size_t i = (size_t)blockIdx.x * 256 + threadIdx.x;   // float4 index
    const size_t off = (size_t)OUT_D * D_FEAT / 4;
    const float4* pv = reinterpret_cast<const float4*>(p);
    float4 a = pv[i], b = pv[i + off], c = pv[i + 2 * off], d = pv[i + 3 * off];
    float4 s = make_float4((a.x + b.x) + (c.x + d.x), (a.y + b.y) + (c.y + d.y),
                           (a.z + b.z) + (c.z + d.z), (a.w + b.w) + (c.w + d.w));
    __nv_bfloat16 h0, l0, h1, l1, h2, l2, h3, l3;
    split_f32(s.x, h0, l0); split_f32(s.y, h1, l1);
    split_f32(s.z, h2, l2); split_f32(s.w, h3, l3);
    reinterpret_cast<ushort4*>(hi)[i] = make_ushort4(
        __bfloat16_as_ushort(h0), __bfloat16_as_ushort(h1),
        __bfloat16_as_ushort(h2), __bfloat16_as_ushort(h3));
    reinterpret_cast<ushort4*>(lo)[i] = make_ushort4(
        __bfloat16_as_ushort(l0), __bfloat16_as_ushort(l1),
        __bfloat16_as_ushort(l2), __bfloat16_as_ushort(l3));
}

// ---------------------------------------------- reduce 2 partials -> fp32 out
__global__ void reduce2_kernel(const float* __restrict__ p, float* __restrict__ out) {
    const size_t i = (size_t)blockIdx.x * 256 + threadIdx.x;   // float4 index
    const size_t off = (size_t)OUT_D * N_SAMP / 4;
    const float4* pv = reinterpret_cast<const float4*>(p);
    float4 a = pv[i], b = pv[i + off];
    reinterpret_cast<float4*>(out)[i] = make_float4(a.x + b.x, a.y + b.y, a.z + b.z, a.w + b.w);
}

// ---------------------------------------------------------------- launch
extern "C" void kernel_launch(void* const* d_in, const int* in_sizes, int n_in,
                              void* d_out, int out_size) {
    (void)n_in; (void)out_size;

    const float* x;
    const float* Psi;
    if (in_sizes[0] == D_FEAT * N_SAMP) {
        x   = (const float*)d_in[0];
        Psi = (const float*)d_in[1];
    } else {
        x   = (const float*)d_in[1];
        Psi = (const float*)d_in[0];
    }
    float* out = (float*)d_out;

    __nv_bfloat16 *psi_hi, *psi_lo, *x_hi, *x_lo, *xt_hi, *xt_lo, *tmp_hi, *tmp_lo;
    float *part1, *part2;
    cudaGetSymbolAddress((void**)&psi_hi, g_psi_hi);
    cudaGetSymbolAddress((void**)&psi_lo, g_psi_lo);
    cudaGetSymbolAddress((void**)&x_hi,   g_x_hi);
    cudaGetSymbolAddress((void**)&x_lo,   g_x_lo);
    cudaGetSymbolAddress((void**)&xt_hi,  g_xt_hi);
    cudaGetSymbolAddress((void**)&xt_lo,  g_xt_lo);
    cudaGetSymbolAddress((void**)&tmp_hi, g_tmp_hi);
    cudaGetSymbolAddress((void**)&tmp_lo, g_tmp_lo);
    cudaGetSymbolAddress((void**)&part1,  g_part1);
    cudaGetSymbolAddress((void**)&part2,  g_part2);

    const int SMEM_BYTES = 3 * STG_BYTES;   // 98304
    cudaFuncSetAttribute(gemm_hmma, cudaFuncAttributeMaxDynamicSharedMemorySize, SMEM_BYTES);

    // 1) Psi: mean + center + bf16 split
    mean_center_split_kernel<<<OUT_D, 256>>>(Psi, psi_hi, psi_lo);

    // 2) x: split (both layouts)
    {
        dim3 grid(N_SAMP / 32, D_FEAT / 32);
        x_split_all_kernel<<<grid, dim3(32, 8)>>>(x, x_hi, x_lo, xt_hi, xt_lo);
    }

    // 3) GEMM1 split-K4: part1[z] = Psi_c . x^T over K-slab z   (2048 tiles)
    {
        dim3 grid(OUT_D / 128, D_FEAT / 128, 4);   // (16, 32, 4)
        gemm_hmma<<<grid, 256, SMEM_BYTES>>>(
            psi_hi, psi_lo, x_hi, x_lo, part1, D_FEAT, N_SAMP, N_SAMP / 4);
    }
    // 3b) reduce 4 partials -> tmp hi/lo
    reduce4_split_kernel<<<(OUT_D * D_FEAT / 4) / 256, 256>>>(part1, tmp_hi, tmp_lo);

    // 4) GEMM2 split-K2: part2[z] = tmp . xt^T over K-slab z    (2048 tiles)
    {
        dim3 grid(OUT_D / 128, N_SAMP / 128, 2);   // (16, 64, 2)
        gemm_hmma<<<grid, 256, SMEM_BYTES>>>(
            tmp_hi, tmp_lo, xt_hi, xt_lo, part2, N_SAMP, D_FEAT, D_FEAT / 2);
    }
    // 4b) reduce 2 partials -> out
    reduce2_kernel<<<(OUT_D * N_SAMP / 4) / 256, 256>>>(part2, out);
}

// round 6
// speedup vs baseline: 3.4383x; 1.0544x over previous
#include <cuda_runtime.h>
#include <cuda_bf16.h>
#include <cstdint>

// ---------------------------------------------------------------- shapes
#define D_FEAT 4096
#define N_SAMP 8192
#define OUT_D  2048

// ---------------------------------------------------------------- scratch
__device__ __nv_bfloat16 g_psi_hi[(size_t)OUT_D * N_SAMP];
__device__ __nv_bfloat16 g_psi_lo[(size_t)OUT_D * N_SAMP];
__device__ __nv_bfloat16 g_x_hi[(size_t)D_FEAT * N_SAMP];
__device__ __nv_bfloat16 g_x_lo[(size_t)D_FEAT * N_SAMP];
__device__ __nv_bfloat16 g_tmp_hi[(size_t)OUT_D * D_FEAT];
__device__ __nv_bfloat16 g_tmp_lo[(size_t)OUT_D * D_FEAT];
__device__ float g_part1[(size_t)4 * OUT_D * D_FEAT];
__device__ float g_part2[(size_t)2 * OUT_D * N_SAMP];

// ---------------------------------------------------------------- helpers
__device__ __forceinline__ uint32_t smem_u32(const void* p) {
    uint32_t a;
    asm("{ .reg .u64 t; cvta.to.shared.u64 t, %1; cvt.u32.u64 %0, t; }" : "=r"(a) : "l"(p));
    return a;
}
__device__ __forceinline__ void cpasync16(uint32_t s, const void* g) {
    asm volatile("cp.async.cg.shared.global [%0], [%1], 16;" :: "r"(s), "l"(g));
}
__device__ __forceinline__ void cp_commit() {
    asm volatile("cp.async.commit_group;" ::: "memory");
}
__device__ __forceinline__ void cp_wait1() {
    asm volatile("cp.async.wait_group 1;" ::: "memory");
}
__device__ __forceinline__ void ldsm4(uint32_t* r, uint32_t addr) {
    asm volatile("ldmatrix.sync.aligned.m8n8.x4.shared.b16 {%0,%1,%2,%3}, [%4];"
                 : "=r"(r[0]), "=r"(r[1]), "=r"(r[2]), "=r"(r[3]) : "r"(addr));
}
__device__ __forceinline__ void ldsm4t(uint32_t* r, uint32_t addr) {
    asm volatile("ldmatrix.sync.aligned.m8n8.x4.trans.shared.b16 {%0,%1,%2,%3}, [%4];"
                 : "=r"(r[0]), "=r"(r[1]), "=r"(r[2]), "=r"(r[3]) : "r"(addr));
}
__device__ __forceinline__ void mma16816(float* c, const uint32_t* a, const uint32_t* b) {
    asm volatile("mma.sync.aligned.m16n8k16.row.col.f32.bf16.bf16.f32 "
                 "{%0,%1,%2,%3}, {%4,%5,%6,%7}, {%8,%9}, {%0,%1,%2,%3};"
                 : "+f"(c[0]), "+f"(c[1]), "+f"(c[2]), "+f"(c[3])
                 : "r"(a[0]), "r"(a[1]), "r"(a[2]), "r"(a[3]), "r"(b[0]), "r"(b[1]));
}
__device__ __forceinline__ void split_f32(float v, __nv_bfloat16& h, __nv_bfloat16& l) {
    h = __float2bfloat16(v);
    l = __float2bfloat16(v - __bfloat162float(h));
}
__device__ __forceinline__ uint32_t sw64(uint32_t off) {
    return off ^ ((off >> 3) & 0x30);
}
__device__ __forceinline__ uint32_t sw128(uint32_t off) {
    return off ^ ((off >> 3) & 0x70);
}

// ------------------------------------------------- fused prep:
// blocks [0, OUT_D): Psi row mean+center+split
// blocks [OUT_D, OUT_D + XCHUNKS): x streaming split
#define XCHUNKS ((D_FEAT * (N_SAMP / 4)) / 256)

__global__ void prep_kernel(const float* __restrict__ Psi, const float* __restrict__ x,
                            __nv_bfloat16* __restrict__ phi, __nv_bfloat16* __restrict__ plo,
                            __nv_bfloat16* __restrict__ xh, __nv_bfloat16* __restrict__ xl) {
    if (blockIdx.x < OUT_D) {
        const int row = blockIdx.x;
        const float4* p = reinterpret_cast<const float4*>(Psi) + (size_t)row * (N_SAMP / 4);
        float4 v[8];
        float s = 0.f;
        #pragma unroll
        for (int q = 0; q < 8; ++q) {
            v[q] = p[q * 256 + threadIdx.x];
            s += (v[q].x + v[q].y) + (v[q].z + v[q].w);
        }
        __shared__ float red[256];
        red[threadIdx.x] = s;
        __syncthreads();
        #pragma unroll
        for (int off = 128; off > 0; off >>= 1) {
            if (threadIdx.x < off) red[threadIdx.x] += red[threadIdx.x + off];
            __syncthreads();
        }
        const float m = red[0] * (1.0f / N_SAMP);
        ushort4* hp = reinterpret_cast<ushort4*>(phi) + (size_t)row * (N_SAMP / 4);
        ushort4* lp = reinterpret_cast<ushort4*>(plo) + (size_t)row * (N_SAMP / 4);
        #pragma unroll
        for (int q = 0; q < 8; ++q) {
            float4 w = v[q];
            w.x -= m; w.y -= m; w.z -= m; w.w -= m;
            __nv_bfloat16 h0, l0, h1, l1, h2, l2, h3, l3;
            split_f32(w.x, h0, l0); split_f32(w.y, h1, l1);
            split_f32(w.z, h2, l2); split_f32(w.w, h3, l3);
            hp[q * 256 + threadIdx.x] = make_ushort4(
                __bfloat16_as_ushort(h0), __bfloat16_as_ushort(h1),
                __bfloat16_as_ushort(h2), __bfloat16_as_ushort(h3));
            lp[q * 256 + threadIdx.x] = make_ushort4(
                __bfloat16_as_ushort(l0), __bfloat16_as_ushort(l1),
                __bfloat16_as_ushort(l2), __bfloat16_as_ushort(l3));
        }
    } else {
        const size_t i = (size_t)(blockIdx.x - OUT_D) * 256 + threadIdx.x;
        float4 v = reinterpret_cast<const float4*>(x)[i];
        __nv_bfloat16 h0, l0, h1, l1, h2, l2, h3, l3;
        split_f32(v.x, h0, l0); split_f32(v.y, h1, l1);
        split_f32(v.z, h2, l2); split_f32(v.w, h3, l3);
        reinterpret_cast<ushort4*>(xh)[i] = make_ushort4(
            __bfloat16_as_ushort(h0), __bfloat16_as_ushort(h1),
            __bfloat16_as_ushort(h2), __bfloat16_as_ushort(h3));
        reinterpret_cast<ushort4*>(xl)[i] = make_ushort4(
            __bfloat16_as_ushort(l0), __bfloat16_as_ushort(l1),
            __bfloat16_as_ushort(l2), __bfloat16_as_ushort(l3));
    }
}

// ---------------------------------------------------------------- HMMA GEMM (split-K)
// Cpart[z][M,N] = (Ahi+Alo)[M, kz:kz+klen] * B_slab^T via hi*hi + hi*lo + lo*hi.
// BTRANS=0: B is [N, K] row-major K-contiguous (non-trans ldsm, SW64 64B rows).
// BTRANS=1: B is [K, ldb] row-major N-contiguous (trans ldsm, [32][128] tile as
//           two SW128 64-col subtiles).
// CTA 128x128, 256 threads (8 warps, warp tile 32x64), K_TILE=32,
// 3-stage cp.async ring (96KB), 2 CTAs/SM. Plain fp32 partial stores.
#define STG_BYTES 32768
#define AH_OFF 0
#define AL_OFF 8192
#define BH_OFF 16384
#define BL_OFF 24576

template <int BTRANS>
__global__ void __launch_bounds__(256, 2)
gemm_hmma(const __nv_bfloat16* __restrict__ Ahi, const __nv_bfloat16* __restrict__ Alo,
          const __nv_bfloat16* __restrict__ Bhi, const __nv_bfloat16* __restrict__ Blo,
          float* __restrict__ Cpart,
          int N, int K, int klen, int ldb) {
    extern __shared__ char smem[];
    const uint32_t sb = smem_u32(smem);

    const int tid  = threadIdx.x;
    const int wid  = tid >> 5;
    const int lane = tid & 31;
    const int wm   = wid & 3;
    const int wn   = wid >> 2;
    const int m0   = blockIdx.x * 128;
    const int n0   = blockIdx.y * 128;
    const int kz   = blockIdx.z * klen;
    float* C = Cpart + (size_t)blockIdx.z * ((size_t)gridDim.x * 128) * N;

    // A loader: 2 chunks/thread (512 chunks of 16B per 128x32 array)
    uint32_t soffA[2];
    size_t gA[2];
    // B loader
    uint32_t soffB[2];
    size_t gB[2];
    #pragma unroll
    for (int q = 0; q < 2; ++q) {
        const int id = q * 256 + tid;
        {
            const int r = id >> 2, sg = id & 3;
            soffA[q] = sw64((uint32_t)(r * 64 + sg * 16));
            gA[q]    = (size_t)(m0 + r) * K + kz + sg * 8;
        }
        if (BTRANS == 0) {
            const int r = id >> 2, sg = id & 3;
            soffB[q] = sw64((uint32_t)(r * 64 + sg * 16));
            gB[q]    = (size_t)(n0 + r) * (size_t)ldb + kz + sg * 8;
        } else {
            const int r = id >> 4, c = id & 15;     // 32 k-rows x 16 chunks
            const int sub = c >> 3;                  // n-col >= 64 -> subtile 1
            soffB[q] = sub * 4096 + sw128((uint32_t)(r * 128 + (c & 7) * 16));
            gB[q]    = (size_t)(kz + r) * (size_t)ldb + n0 + c * 8;
        }
    }

    auto load_stage = [&](int t) {
        const uint32_t base = sb + (t % 3) * STG_BYTES;
        const size_t ka = (size_t)t * 32;
        const size_t kb = BTRANS ? (size_t)t * 32 * (size_t)ldb : (size_t)t * 32;
        #pragma unroll
        for (int q = 0; q < 2; ++q) {
            cpasync16(base + AH_OFF + soffA[q], Ahi + gA[q] + ka);
            cpasync16(base + AL_OFF + soffA[q], Alo + gA[q] + ka);
            cpasync16(base + BH_OFF + soffB[q], Bhi + gB[q] + kb);
            cpasync16(base + BL_OFF + soffB[q], Blo + gB[q] + kb);
        }
        cp_commit();
    };

    const int quad = lane >> 3, l8 = lane & 7;
    const int a_row  = wm * 32 + (quad & 1) * 8 + l8;
    const int a_colq = (quad >> 1) * 8;
    // B lane components
    //  BTRANS=0: row = n, col = k    BTRANS=1: row = k, col = n
    const int b_row0 = wn * 64 + (quad >> 1) * 8 + l8;   // + j*16        (non-trans)
    const int b_col0 = (quad & 1) * 8;                   // + k0
    const int b_kq   = (quad & 1) * 8 + l8;              // + k0          (trans)
    const int b_nq   = wn * 64 + (quad >> 1) * 8;        // + j*16

    float acc[2][8][4];
    #pragma unroll
    for (int i = 0; i < 2; ++i)
        #pragma unroll
        for (int j = 0; j < 8; ++j)
            #pragma unroll
            for (int e = 0; e < 4; ++e) acc[i][j][e] = 0.f;

    const int ntiles = klen / 32;
    load_stage(0);
    load_stage(1);

    for (int s = 0; s < ntiles; ++s) {
        cp_wait1();
        __syncthreads();
        if (s + 2 < ntiles) load_stage(s + 2);

        const uint32_t st = sb + (s % 3) * STG_BYTES;
        #pragma unroll
        for (int h = 0; h < 2; ++h) {
            const int k0 = h * 16;
            uint32_t Ah[2][4], Al[2][4];
            #pragma unroll
            for (int i = 0; i < 2; ++i) {
                const uint32_t ao = sw64((uint32_t)((a_row + i * 16) * 64 + (k0 + a_colq) * 2));
                ldsm4(Ah[i], st + AH_OFF + ao);
                ldsm4(Al[i], st + AL_OFF + ao);
            }
            #pragma unroll
            for (int jj = 0; jj < 2; ++jj) {
                uint32_t Bh[2][4], Bl[2][4];
                #pragma unroll
                for (int j = 0; j < 2; ++j) {
                    uint32_t bo;
                    if (BTRANS == 0) {
                        bo = sw64((uint32_t)((b_row0 + (jj * 2 + j) * 16) * 64 + (k0 + b_col0) * 2));
                        ldsm4(Bh[j], st + BH_OFF + bo);
                        ldsm4(Bl[j], st + BL_OFF + bo);
                    } else {
                        const int ncol = b_nq + (jj * 2 + j) * 16;
                        const int sub  = ncol >> 6;
                        bo = sub * 4096 + sw128((uint32_t)((k0 + b_kq) * 128 + (ncol & 63) * 2));
                        ldsm4t(Bh[j], st + BH_OFF + bo);
                        ldsm4t(Bl[j], st + BL_OFF + bo);
                    }
                }
                #pragma unroll
                for (int i = 0; i < 2; ++i)
                    #pragma unroll
                    for (int j = 0; j < 4; ++j) {
                        float* c = acc[i][jj * 4 + j];
                        const uint32_t* bh = &Bh[j >> 1][(j & 1) * 2];
                        const uint32_t* bl = &Bl[j >> 1][(j & 1) * 2];
                        mma16816(c, Ah[i], bh);
                        mma16816(c, Ah[i], bl);
                        mma16816(c, Al[i], bh);
                    }
            }
        }
    }

    // ---- epilogue: plain fp32 partial stores
    const int r_base = m0 + wm * 32 + (lane >> 2);
    const int c_base = n0 + wn * 64 + (lane & 3) * 2;
    #pragma unroll
    for (int i = 0; i < 2; ++i) {
        #pragma unroll
        for (int j = 0; j < 8; ++j) {
            const int r0 = r_base + i * 16;
            const int c  = c_base + j * 8;
            *reinterpret_cast<float2*>(C + (size_t)r0 * N + c) =
                make_float2(acc[i][j][0], acc[i][j][1]);
            *reinterpret_cast<float2*>(C + (size_t)(r0 + 8) * N + c) =
                make_float2(acc[i][j][2], acc[i][j][3]);
        }
    }
}

// ---------------------------------------------- reduce 4 partials -> bf16 hi/lo
__global__ void reduce4_split_kernel(const float* __restrict__ p,
                                     __nv_bfloat16* __restrict__ hi,
                                     __nv_bfloat16* __restrict__ lo) {
    const size_t i = (size_t)blockIdx.x * 256 + threadIdx.x;
    const size_t off = (size_t)OUT_D * D_FEAT / 4;
    const float4* pv = reinterpret_cast<const float4*>(p);
    float4 a = pv[i], b = pv[i + off], c = pv[i + 2 * off], d = pv[i + 3 * off];
    float4 s = make_float4((a.x + b.x) + (c.x + d.x), (a.y + b.y) + (c.y + d.y),
                           (a.z + b.z) + (c.z + d.z), (a.w + b.w) + (c.w + d.w));
    __nv_bfloat16 h0, l0, h1, l1, h2, l2, h3, l3;
    split_f32(s.x, h0, l0); split_f32(s.y, h1, l1);
    split_f32(s.z, h2, l2); split_f32(s.w, h3, l3);
    reinterpret_cast<ushort4*>(hi)[i] = make_ushort4(
        __bfloat16_as_ushort(h0), __bfloat16_as_ushort(h1),
        __bfloat16_as_ushort(h2), __bfloat16_as_ushort(h3));
    reinterpret_cast<ushort4*>(lo)[i] = make_ushort4(
        __bfloat16_as_ushort(l0), __bfloat16_as_ushort(l1),
        __bfloat16_as_ushort(l2), __bfloat16_as_ushort(l3));
}

// ---------------------------------------------- reduce 2 partials -> fp32 out
__global__ void reduce2_kernel(const float* __restrict__ p, float* __restrict__ out) {
    const size_t i = (size_t)blockIdx.x * 256 + threadIdx.x;
    const size_t off = (size_t)OUT_D * N_SAMP / 4;
    const float4* pv = reinterpret_cast<const float4*>(p);
    float4 a = pv[i], b = pv[i + off];
    reinterpret_cast<float4*>(out)[i] = make_float4(a.x + b.x, a.y + b.y, a.z + b.z, a.w + b.w);
}

// ---------------------------------------------------------------- launch
extern "C" void kernel_launch(void* const* d_in, const int* in_sizes, int n_in,
                              void* d_out, int out_size) {
    (void)n_in; (void)out_size;

    const float* x;
    const float* Psi;
    if (in_sizes[0] == D_FEAT * N_SAMP) {
        x   = (const float*)d_in[0];
        Psi = (const float*)d_in[1];
    } else {
        x   = (const float*)d_in[1];
        Psi = (const float*)d_in[0];
    }
    float* out = (float*)d_out;

    __nv_bfloat16 *psi_hi, *psi_lo, *x_hi, *x_lo, *tmp_hi, *tmp_lo;
    float *part1, *part2;
    cudaGetSymbolAddress((void**)&psi_hi, g_psi_hi);
    cudaGetSymbolAddress((void**)&psi_lo, g_psi_lo);
    cudaGetSymbolAddress((void**)&x_hi,   g_x_hi);
    cudaGetSymbolAddress((void**)&x_lo,   g_x_lo);
    cudaGetSymbolAddress((void**)&tmp_hi, g_tmp_hi);
    cudaGetSymbolAddress((void**)&tmp_lo, g_tmp_lo);
    cudaGetSymbolAddress((void**)&part1,  g_part1);
    cudaGetSymbolAddress((void**)&part2,  g_part2);

    const int SMEM_BYTES = 3 * STG_BYTES;   // 98304
    cudaFuncSetAttribute(gemm_hmma<0>, cudaFuncAttributeMaxDynamicSharedMemorySize, SMEM_BYTES);
    cudaFuncSetAttribute(gemm_hmma<1>, cudaFuncAttributeMaxDynamicSharedMemorySize, SMEM_BYTES);

    // 1) fused prep: Psi mean+center+split, x streaming split
    prep_kernel<<<OUT_D + XCHUNKS, 256>>>(Psi, x, psi_hi, psi_lo, x_hi, x_lo);

    // 2) GEMM1 split-K4: part1[z] = Psi_c . x^T over K-slab z (B non-trans)
    {
        dim3 grid(OUT_D / 128, D_FEAT / 128, 4);   // (16, 32, 4)
        gemm_hmma<0><<<grid, 256, SMEM_BYTES>>>(
            psi_hi, psi_lo, x_hi, x_lo, part1, D_FEAT, N_SAMP, N_SAMP / 4, N_SAMP);
    }
    // 2b) reduce 4 partials -> tmp hi/lo
    reduce4_split_kernel<<<(OUT_D * D_FEAT / 4) / 256, 256>>>(part1, tmp_hi, tmp_lo);

    // 3) GEMM2 split-K2: part2[z] = tmp . x over K-slab z (B = x[d,n], trans ldsm)
    {
        dim3 grid(OUT_D / 128, N_SAMP / 128, 2);   // (16, 64, 2)
        gemm_hmma<1><<<grid, 256, SMEM_BYTES>>>(
            tmp_hi, tmp_lo, x_hi, x_lo, part2, N_SAMP, D_FEAT, D_FEAT / 2, N_SAMP);
    }
    // 3b) reduce 2 partials -> out
    reduce2_kernel<<<(OUT_D * N_SAMP / 4) / 256, 256>>>(part2, out);
}